// round 15
// baseline (speedup 1.0000x reference)
#include <cuda_runtime.h>
#include <cuda_fp16.h>
#include <cstdint>
#include <math.h>

// ---------------- problem constants ----------------
#define B_    16
#define CIN   48
#define COUT  48
#define HH    128
#define WW    128
#define SP    7
#define TAPS  49
#define KDIM  98

// ---------------- tiling ----------------
#define NCHUNK 3                   // chunks of 16 channels (K=16 per mma)
#define RG     2                   // output rows per tile
#define SLAB_RR 8                  // RG + 6 halo
#define SLAB_CC 134                // 128 + 6 halo
#define PLANE_B (SLAB_RR*SLAB_CC*16)     // 17152 bytes
#define SLAB_B  (2*PLANE_B)              // 34304
#define FBUF_B  (SP*1536)                // 10752 (one kernel row = 7 taps)
#define TILEIDX_OFF (SLAB_B + 2*FBUF_B)  // 55808: dedicated steal-idx slot
#define SMEMT   (TILEIDX_OFF + 16)       // 55824 -> 3 CTAs/SM

#define NTHREADS 256
#define NTILES   (B_ * 64)         // 1024

// fp16 NHWC input: x_h[b][h][w][c48]
__device__ __half g_xh[(size_t)B_ * HH * WW * CIN];
// filter scratch: g_F[b][chunk3][tap49][plane2][n48][mm8] (fp16)
__device__ __half g_F[(size_t)B_ * NCHUNK * TAPS * 2 * 48 * 8];
// work-stealing counter (reset by prep kernel each launch/replay)
__device__ int g_ctr = 0;

// ---------------- helpers ----------------
__device__ __forceinline__ void mma_f16(float* c, uint32_t a0, uint32_t a1,
                                        uint32_t a2, uint32_t a3,
                                        uint32_t b0, uint32_t b1) {
    asm volatile(
        "mma.sync.aligned.m16n8k16.row.col.f32.f16.f16.f32 "
        "{%0,%1,%2,%3},{%4,%5,%6,%7},{%8,%9},{%0,%1,%2,%3};"
        : "+f"(c[0]), "+f"(c[1]), "+f"(c[2]), "+f"(c[3])
        : "r"(a0), "r"(a1), "r"(a2), "r"(a3), "r"(b0), "r"(b1));
}
__device__ __forceinline__ void ldsm_x4(uint32_t& r0, uint32_t& r1,
                                        uint32_t& r2, uint32_t& r3, uint32_t addr) {
    asm volatile("ldmatrix.sync.aligned.m8n8.x4.shared.b16 {%0,%1,%2,%3}, [%4];"
                 : "=r"(r0), "=r"(r1), "=r"(r2), "=r"(r3) : "r"(addr));
}
__device__ __forceinline__ void cp16(uint32_t dst, const void* src) {
    asm volatile("cp.async.cg.shared.global [%0], [%1], 16;" :: "r"(dst), "l"(src));
}
#define CP_COMMIT() asm volatile("cp.async.commit_group;" ::: "memory")
#define CP_WAIT0()  asm volatile("cp.async.wait_group 0;" ::: "memory")

// ---------------------------------------------------------------------------
// Kernel P: blocks [0,2048) NCHW->NHWC fp16; [2048,2240) filter generation.
// Block 0 also resets the steal counter (stream-ordered before conv kernel).
// ---------------------------------------------------------------------------
__global__ __launch_bounds__(256)
void prep_kernel(const float* __restrict__ x,
                 const float* __restrict__ theta,
                 const float* __restrict__ W)
{
    __shared__ __half tr[CIN][WW + 2];
    __shared__ float  bs[TAPS][KDIM];

    const int t = threadIdx.x;

    if (blockIdx.x == 0 && t == 0) g_ctr = 0;   // reset steal counter

    if (blockIdx.x < 2048) {
        const int h = blockIdx.x & 127;
        const int b = blockIdx.x >> 7;

        for (int idx = t; idx < CIN * WW; idx += 256) {
            const int c = idx >> 7;
            const int w = idx & 127;
            tr[c][w] = __float2half_rn(x[(((size_t)b * CIN + c) * HH + h) * WW + w]);
        }
        __syncthreads();

        uint4* dst = (uint4*)(g_xh + ((size_t)b * HH + h) * WW * CIN);
        for (int q = t; q < WW * 6; q += 256) {
            const int w  = q / 6;
            const int cg = q - w * 6;
            __half tmp[8];
            #pragma unroll
            for (int k = 0; k < 8; ++k) tmp[k] = tr[cg * 8 + k][w];
            dst[q] = *(uint4*)tmp;
        }
        return;
    }

    const int blk = blockIdx.x - 2048;
    const int nh = blk & 1;
    const int ch = (blk >> 1) % 6;
    const int b  = blk / 12;

    const float th = theta[b];
    const float ct = cosf(th), st = sinf(th);

    for (int e = t; e < TAPS * KDIM; e += 256) {
        const int tap = e / KDIM;
        const int q   = e - tap * KDIM;
        const int i   = tap / SP;
        const int j   = tap % SP;
        const float xj = (float)(j - 3) * (1.0f / 3.0f);
        const float xi = (float)(i - 3) * (1.0f / 3.0f);
        const float Xr = ct * xj - st * xi;
        const float Yr = st * xj + ct * xi;
        const float r2 = Xr * Xr + Yr * Yr;
        const float mask = expf(-fmaxf(r2 - 1.0f, 0.0f) * 5.0f);

        const bool cosp = (q < TAPS);
        const int  qq   = cosp ? q : q - TAPS;
        const int  k    = qq / SP;
        const int  l    = qq % SP;
        const float kk = (k > 3) ? (float)(k - SP) : (float)k;
        const float ll = (l > 3) ? (float)(l - SP) : (float)l;
        const float v  = 2.6927937030769655f;   // pi/7 * 6
        const float ang = kk * v * Xr + ll * v * Yr;
        bs[tap][q] = (cosp ? cosf(ang) : sinf(ang)) * mask;
    }
    __syncthreads();

    if (t >= 96) return;
    const int nn = t >> 3;
    const int mm = t & 7;
    const int m  = ch * 8 + mm;
    const int n0 = nh * 24 + nn;

    float acc0[TAPS], acc1[TAPS];
    #pragma unroll
    for (int tap = 0; tap < TAPS; ++tap) { acc0[tap] = 0.f; acc1[tap] = 0.f; }

    const float* w0 = W + (size_t)n0 * KDIM * CIN + m;
    const float* w1 = w0 + (size_t)12 * KDIM * CIN;

    #pragma unroll 2
    for (int k = 0; k < KDIM; ++k) {
        const float v0 = w0[(size_t)k * CIN];
        const float v1 = w1[(size_t)k * CIN];
        #pragma unroll
        for (int tap = 0; tap < TAPS; ++tap) {
            const float f = bs[tap][k];
            acc0[tap] = fmaf(f, v0, acc0[tap]);
            acc1[tap] = fmaf(f, v1, acc1[tap]);
        }
    }

    const int chunk = ch >> 1, plane = ch & 1;
    __half* Fo = g_F + ((((size_t)(b * NCHUNK + chunk) * TAPS) * 2 + plane) * 48) * 8 + mm;
    #pragma unroll
    for (int tap = 0; tap < TAPS; ++tap) {
        __half* Ft = Fo + (size_t)tap * (2 * 48 * 8);
        Ft[(size_t)n0 * 8]        = __float2half_rn(acc0[tap]);
        Ft[(size_t)(n0 + 12) * 8] = __float2half_rn(acc1[tap]);
    }
}

// ---------------------------------------------------------------------------
// Tile-prologue staging helpers (device inline, used by conv kernel)
// ---------------------------------------------------------------------------
struct ConvCtx {
    uint32_t slab_u, filt_u;
    int f_w, f_pl, tid;
};

__device__ __forceinline__ void rezero_oob_rows(const ConvCtx& c, unsigned char* smraw,
                                                int rg, int h0) {
    if (rg <= 1 || rg >= 62) {
        #pragma unroll 1
        for (int rr = 0; rr < SLAB_RR; ++rr) {
            const int gr = h0 - 3 + rr;
            if (gr >= 0 && gr < HH) continue;
            for (int q = c.tid; q < 2 * SLAB_CC; q += NTHREADS) {
                const int pl = q / SLAB_CC;
                const int cc = q - pl * SLAB_CC;
                *(uint4*)(smraw + (size_t)((pl * SLAB_RR + rr) * SLAB_CC + cc) * 16)
                    = make_uint4(0, 0, 0, 0);
            }
        }
    }
}

__device__ __forceinline__ void issue_tile_prologue(const ConvCtx& c,
                                                    const __half* xhb,
                                                    const char* Fbb, int h0) {
    #pragma unroll 1
    for (int rr = 0; rr < SLAB_RR; ++rr) {
        const int gr = h0 - 3 + rr;
        if (gr < 0 || gr >= HH) continue;
        const char* src = (const char*)(xhb + (size_t)gr * WW * CIN)
                        + (c.f_w * 6 + c.f_pl) * 16;
        cp16(c.slab_u + (uint32_t)(((c.f_pl * SLAB_RR + rr) * SLAB_CC + 3 + c.f_w) * 16), src);
    }
    for (int q = c.tid; q < SP * 96; q += NTHREADS)
        cp16(c.filt_u + q * 16, Fbb + q * 16);
    CP_COMMIT();
}

// ---------------------------------------------------------------------------
// Kernel B: fp16 m16n8k16 implicit-GEMM grouped conv, atomic work stealing.
// 256 thr, 3 CTAs/SM. Next tile's steal + prologue (OOB re-zero, slab chunk0,
// filt group0) are issued BEFORE the current tile's epilogue, hiding the
// cp.async latency behind global stores.
// ---------------------------------------------------------------------------
__global__ __launch_bounds__(NTHREADS, 3)
void conv_mma_kernel(const float* __restrict__ cbias,
                     float* __restrict__ y)
{
    extern __shared__ __align__(16) unsigned char smraw[];
    const uint32_t smem_u = (uint32_t)__cvta_generic_to_shared(smraw);
    ConvCtx c;
    c.slab_u = smem_u;
    c.filt_u = smem_u + SLAB_B;
    c.tid    = threadIdx.x;
    c.f_w    = threadIdx.x >> 1;
    c.f_pl   = threadIdx.x & 1;
    int* steal_slot = (int*)(smraw + TILEIDX_OFF);

    const int tid  = threadIdx.x;
    const int wid  = tid >> 5;
    const int lane = tid & 31;
    const int g8 = lane >> 2;
    const int t4 = lane & 3;
    const int rw   = wid & 1;          // warp row 0..1
    const int col0 = (wid >> 1) * 32;  // warp col base

    const uint32_t a_lane = c.slab_u + (uint32_t)((lane >> 4) * PLANE_B + (lane & 15) * 16);
    const uint32_t b4off  = (uint32_t)(((lane >> 3) & 1) * (48 * 16)
                                       + ((lane >> 4) * 8 + (lane & 7)) * 16);

    // zero whole slab once (halo cols stay zero forever; never filled)
    for (int q = tid; q < SLAB_B / 16; q += NTHREADS)
        ((uint4*)smraw)[q] = make_uint4(0, 0, 0, 0);

    // ---- initial steal + prologue ----
    __syncthreads();
    if (tid == 0) *steal_slot = atomicAdd(&g_ctr, 1);
    __syncthreads();
    int tile = *steal_slot;
    if (tile < NTILES) {
        const int rg0 = tile & 63;
        rezero_oob_rows(c, smraw, rg0, rg0 * RG);
        // (rezero and fill touch disjoint rows; no sync needed between them)
        issue_tile_prologue(c,
            g_xh + (size_t)(tile >> 6) * HH * WW * CIN,
            (const char*)(g_F + (size_t)(tile >> 6) * NCHUNK * TAPS * 768),
            rg0 * RG);
        CP_WAIT0();
    }
    __syncthreads();

    while (tile < NTILES) {
        const int b  = tile >> 6;
        const int rg = tile & 63;
        const int h0 = rg * RG;

        float acc[2][6][4];
        #pragma unroll
        for (int mt = 0; mt < 2; ++mt)
            #pragma unroll
            for (int nt = 0; nt < 6; ++nt)
                #pragma unroll
                for (int q = 0; q < 4; ++q)
                    acc[mt][nt][q] = 0.0f;

        const __half* xhb = g_xh + (size_t)b * HH * WW * CIN;
        const char*   Fbb = (const char*)(g_F + (size_t)b * NCHUNK * TAPS * 768);

        // mainloop: 21 groups = 3 chunks x 7 kernel rows
        #pragma unroll 1
        for (int chunk = 0; chunk < NCHUNK; ++chunk) {
            #pragma unroll 1
            for (int i = 0; i < SP; ++i) {
                const int g = chunk * SP + i;

                if (g < 3 * SP - 1) {
                    const int gn  = g + 1;
                    const int nck = gn / SP;
                    const int ni  = gn - nck * SP;
                    const char* src = Fbb + ((size_t)nck * TAPS + ni * SP) * 1536;
                    const uint32_t dstb = c.filt_u + (uint32_t)((gn & 1) * FBUF_B);
                    for (int q = tid; q < SP * 96; q += NTHREADS)
                        cp16(dstb + q * 16, src + q * 16);
                    CP_COMMIT();
                }

                const uint32_t fb = c.filt_u + (uint32_t)((g & 1) * FBUF_B) + b4off;
                const uint32_t ar = a_lane
                    + (uint32_t)((rw + i) * (SLAB_CC * 16) + col0 * 16);

                #pragma unroll
                for (int j = 0; j < SP; ++j) {
                    const uint32_t bt = fb + (uint32_t)(j * 1536);
                    uint32_t Bf[6][2];
                    ldsm_x4(Bf[0][0], Bf[0][1], Bf[1][0], Bf[1][1], bt);
                    ldsm_x4(Bf[2][0], Bf[2][1], Bf[3][0], Bf[3][1], bt + 256);
                    ldsm_x4(Bf[4][0], Bf[4][1], Bf[5][0], Bf[5][1], bt + 512);
                    #pragma unroll
                    for (int mt = 0; mt < 2; ++mt) {
                        uint32_t a0, a1, a2, a3;
                        ldsm_x4(a0, a1, a2, a3, ar + (uint32_t)((mt * 16 + j) * 16));
                        #pragma unroll
                        for (int nt = 0; nt < 6; ++nt)
                            mma_f16(acc[mt][nt], a0, a1, a2, a3, Bf[nt][0], Bf[nt][1]);
                    }
                }

                CP_WAIT0();
                __syncthreads();
            }

            if (chunk < NCHUNK - 1) {
                #pragma unroll 1
                for (int rr = 0; rr < SLAB_RR; ++rr) {
                    const int gr = h0 - 3 + rr;
                    if (gr < 0 || gr >= HH) continue;
                    const char* src = (const char*)(xhb + (size_t)gr * WW * CIN)
                                    + (c.f_w * 6 + (chunk + 1) * 2 + c.f_pl) * 16;
                    cp16(c.slab_u + (uint32_t)(((c.f_pl * SLAB_RR + rr) * SLAB_CC + 3 + c.f_w) * 16), src);
                }
                CP_COMMIT();
                CP_WAIT0();
                __syncthreads();
            }
        }
        // here: all reads of slab + filt done (sync after last group)

        // ---- steal next tile, issue ITS prologue before the epilogue ----
        if (tid == 0) *steal_slot = atomicAdd(&g_ctr, 1);
        __syncthreads();
        const int tile_next = *steal_slot;
        if (tile_next < NTILES) {
            const int rgn = tile_next & 63;
            rezero_oob_rows(c, smraw, rgn, rgn * RG);
            issue_tile_prologue(c,
                g_xh + (size_t)(tile_next >> 6) * HH * WW * CIN,
                (const char*)(g_F + (size_t)(tile_next >> 6) * NCHUNK * TAPS * 768),
                rgn * RG);
        }

        // ---- epilogue (overlaps next tile's cp.async arrivals) ----
        const int row = h0 + rw;
        #pragma unroll
        for (int nt = 0; nt < 6; ++nt) {
            const int n  = nt * 8 + 2 * t4;
            const float b0 = __ldg(&cbias[n]);
            const float b1 = __ldg(&cbias[n + 1]);
            float* y0 = y + (((size_t)b * COUT + n) * HH + row) * WW;
            float* y1 = y0 + (size_t)HH * WW;
            #pragma unroll
            for (int mt = 0; mt < 2; ++mt) {
                const int px = col0 + mt * 16 + g8;
                y0[px]     = acc[mt][nt][0] + b0;
                y1[px]     = acc[mt][nt][1] + b1;
                y0[px + 8] = acc[mt][nt][2] + b0;
                y1[px + 8] = acc[mt][nt][3] + b1;
            }
        }

        CP_WAIT0();          // next tile's slab/filt resident (per-thread)
        __syncthreads();     // visible block-wide; also orders rezero stores
        tile = tile_next;
    }
}

// ---------------------------------------------------------------------------
extern "C" void kernel_launch(void* const* d_in, const int* in_sizes, int n_in,
                              void* d_out, int out_size)
{
    const float* x     = (const float*)d_in[0];  // (16,48,128,128)
    const float* theta = (const float*)d_in[1];  // (16,1)
    const float* wts   = (const float*)d_in[2];  // (48,98,48)
    const float* cbias = (const float*)d_in[3];  // (1,48,1,1)
    float*       y     = (float*)d_out;          // (16,48,128,128)

    (void)in_sizes; (void)n_in; (void)out_size;

    static int grid_cached = 0;
    if (!grid_cached) {
        cudaFuncSetAttribute(conv_mma_kernel,
                             cudaFuncAttributeMaxDynamicSharedMemorySize, SMEMT);
        int dev = 0, nsm = 148, occ = 0;
        cudaGetDevice(&dev);
        cudaDeviceGetAttribute(&nsm, cudaDevAttrMultiProcessorCount, dev);
        cudaOccupancyMaxActiveBlocksPerMultiprocessor(&occ, conv_mma_kernel,
                                                      NTHREADS, SMEMT);
        if (occ < 1) occ = 1;
        int g = occ * nsm;
        if (g > NTILES) g = NTILES;
        grid_cached = g;
    }

    prep_kernel<<<2048 + 192, 256>>>(x, theta, wts);
    conv_mma_kernel<<<grid_cached, NTHREADS, SMEMT>>>(cbias, y);
}

// round 16
// speedup vs baseline: 1.0402x; 1.0402x over previous
#include <cuda_runtime.h>
#include <cuda_fp16.h>
#include <cstdint>
#include <math.h>

// ---------------- problem constants ----------------
#define B_    16
#define CIN   48
#define COUT  48
#define HH    128
#define WW    128
#define SP    7
#define TAPS  49
#define KDIM  98

// ---------------- tiling ----------------
#define NCHUNK 3                   // chunks of 16 channels (K=16 per mma)
#define RG     2                   // output rows per tile
#define SLAB_RR 8                  // RG + 6 halo
#define SLAB_CC 134                // 128 + 6 halo
#define PLANE_B (SLAB_RR*SLAB_CC*16)     // 17152 bytes
#define SLAB_B  (2*PLANE_B)              // 34304
#define FBUF_B  (SP*1536)                // 10752 (one kernel row = 7 taps)
#define TILEIDX_OFF (SLAB_B + 2*FBUF_B)  // 55808: dedicated steal-idx slot
#define SMEMT   (TILEIDX_OFF + 16)       // 55824 -> 3 CTAs/SM

#define NTHREADS 256
#define NTILES   (B_ * 64)         // 1024

// fp16 NHWC input: x_h[b][h][w][c48]
__device__ __half g_xh[(size_t)B_ * HH * WW * CIN];
// filter scratch: g_F[b][chunk3][tap49][plane2][n48][mm8] (fp16)
__device__ __half g_F[(size_t)B_ * NCHUNK * TAPS * 2 * 48 * 8];
// work-stealing counter (reset by prep kernel each launch/replay)
__device__ int g_ctr = 0;

// ---------------- helpers ----------------
__device__ __forceinline__ void mma_f16(float* c, uint32_t a0, uint32_t a1,
                                        uint32_t a2, uint32_t a3,
                                        uint32_t b0, uint32_t b1) {
    asm volatile(
        "mma.sync.aligned.m16n8k16.row.col.f32.f16.f16.f32 "
        "{%0,%1,%2,%3},{%4,%5,%6,%7},{%8,%9},{%0,%1,%2,%3};"
        : "+f"(c[0]), "+f"(c[1]), "+f"(c[2]), "+f"(c[3])
        : "r"(a0), "r"(a1), "r"(a2), "r"(a3), "r"(b0), "r"(b1));
}
__device__ __forceinline__ void ldsm_x4(uint32_t& r0, uint32_t& r1,
                                        uint32_t& r2, uint32_t& r3, uint32_t addr) {
    asm volatile("ldmatrix.sync.aligned.m8n8.x4.shared.b16 {%0,%1,%2,%3}, [%4];"
                 : "=r"(r0), "=r"(r1), "=r"(r2), "=r"(r3) : "r"(addr));
}
__device__ __forceinline__ void cp16(uint32_t dst, const void* src) {
    asm volatile("cp.async.cg.shared.global [%0], [%1], 16;" :: "r"(dst), "l"(src));
}
#define CP_COMMIT() asm volatile("cp.async.commit_group;" ::: "memory")
#define CP_WAIT0()  asm volatile("cp.async.wait_group 0;" ::: "memory")

// ---------------------------------------------------------------------------
// Kernel P: blocks [0,2048) NCHW->NHWC fp16; [2048,2240) filter generation.
// Block 0 also resets the steal counter (stream-ordered before conv kernel).
// ---------------------------------------------------------------------------
__global__ __launch_bounds__(256)
void prep_kernel(const float* __restrict__ x,
                 const float* __restrict__ theta,
                 const float* __restrict__ W)
{
    __shared__ __half tr[CIN][WW + 2];
    __shared__ float  bs[TAPS][KDIM];

    const int t = threadIdx.x;

    if (blockIdx.x == 0 && t == 0) g_ctr = 0;   // reset steal counter

    if (blockIdx.x < 2048) {
        const int h = blockIdx.x & 127;
        const int b = blockIdx.x >> 7;

        for (int idx = t; idx < CIN * WW; idx += 256) {
            const int c = idx >> 7;
            const int w = idx & 127;
            tr[c][w] = __float2half_rn(x[(((size_t)b * CIN + c) * HH + h) * WW + w]);
        }
        __syncthreads();

        uint4* dst = (uint4*)(g_xh + ((size_t)b * HH + h) * WW * CIN);
        for (int q = t; q < WW * 6; q += 256) {
            const int w  = q / 6;
            const int cg = q - w * 6;
            __half tmp[8];
            #pragma unroll
            for (int k = 0; k < 8; ++k) tmp[k] = tr[cg * 8 + k][w];
            dst[q] = *(uint4*)tmp;
        }
        return;
    }

    const int blk = blockIdx.x - 2048;
    const int nh = blk & 1;
    const int ch = (blk >> 1) % 6;
    const int b  = blk / 12;

    const float th = theta[b];
    const float ct = cosf(th), st = sinf(th);

    for (int e = t; e < TAPS * KDIM; e += 256) {
        const int tap = e / KDIM;
        const int q   = e - tap * KDIM;
        const int i   = tap / SP;
        const int j   = tap % SP;
        const float xj = (float)(j - 3) * (1.0f / 3.0f);
        const float xi = (float)(i - 3) * (1.0f / 3.0f);
        const float Xr = ct * xj - st * xi;
        const float Yr = st * xj + ct * xi;
        const float r2 = Xr * Xr + Yr * Yr;
        const float mask = expf(-fmaxf(r2 - 1.0f, 0.0f) * 5.0f);

        const bool cosp = (q < TAPS);
        const int  qq   = cosp ? q : q - TAPS;
        const int  k    = qq / SP;
        const int  l    = qq % SP;
        const float kk = (k > 3) ? (float)(k - SP) : (float)k;
        const float ll = (l > 3) ? (float)(l - SP) : (float)l;
        const float v  = 2.6927937030769655f;   // pi/7 * 6
        const float ang = kk * v * Xr + ll * v * Yr;
        bs[tap][q] = (cosp ? cosf(ang) : sinf(ang)) * mask;
    }
    __syncthreads();

    if (t >= 96) return;
    const int nn = t >> 3;
    const int mm = t & 7;
    const int m  = ch * 8 + mm;
    const int n0 = nh * 24 + nn;

    float acc0[TAPS], acc1[TAPS];
    #pragma unroll
    for (int tap = 0; tap < TAPS; ++tap) { acc0[tap] = 0.f; acc1[tap] = 0.f; }

    const float* w0 = W + (size_t)n0 * KDIM * CIN + m;
    const float* w1 = w0 + (size_t)12 * KDIM * CIN;

    #pragma unroll 2
    for (int k = 0; k < KDIM; ++k) {
        const float v0 = w0[(size_t)k * CIN];
        const float v1 = w1[(size_t)k * CIN];
        #pragma unroll
        for (int tap = 0; tap < TAPS; ++tap) {
            const float f = bs[tap][k];
            acc0[tap] = fmaf(f, v0, acc0[tap]);
            acc1[tap] = fmaf(f, v1, acc1[tap]);
        }
    }

    const int chunk = ch >> 1, plane = ch & 1;
    __half* Fo = g_F + ((((size_t)(b * NCHUNK + chunk) * TAPS) * 2 + plane) * 48) * 8 + mm;
    #pragma unroll
    for (int tap = 0; tap < TAPS; ++tap) {
        __half* Ft = Fo + (size_t)tap * (2 * 48 * 8);
        Ft[(size_t)n0 * 8]        = __float2half_rn(acc0[tap]);
        Ft[(size_t)(n0 + 12) * 8] = __float2half_rn(acc1[tap]);
    }
}

// ---------------------------------------------------------------------------
// Kernel B: fp16 m16n8k16 implicit-GEMM grouped conv with atomic work
// stealing (NO inter-CTA waits — cannot deadlock). 256 thr, 3 CTAs/SM.
// Per-tile pipeline = verified R10 conv. Slab-reuse invariant: every row
// whose gr is OOB is re-zeroed per tile (rg<=1 || rg>=62).
// ---------------------------------------------------------------------------
__global__ __launch_bounds__(NTHREADS, 3)
void conv_mma_kernel(const float* __restrict__ cbias,
                     float* __restrict__ y)
{
    extern __shared__ __align__(16) unsigned char smraw[];
    const uint32_t smem_u = (uint32_t)__cvta_generic_to_shared(smraw);
    const uint32_t slab_u = smem_u;
    const uint32_t filt_u = smem_u + SLAB_B;
    int* steal_slot = (int*)(smraw + TILEIDX_OFF);

    const int tid  = threadIdx.x;
    const int wid  = tid >> 5;
    const int lane = tid & 31;
    const int g8 = lane >> 2;
    const int t4 = lane & 3;
    const int rw   = wid & 1;          // warp row 0..1
    const int col0 = (wid >> 1) * 32;  // warp col base

    const uint32_t a_lane = slab_u + (uint32_t)((lane >> 4) * PLANE_B + (lane & 15) * 16);
    const uint32_t b4off  = (uint32_t)(((lane >> 3) & 1) * (48 * 16)
                                       + ((lane >> 4) * 8 + (lane & 7)) * 16);

    const int f_w  = tid >> 1;
    const int f_pl = tid & 1;

    // zero whole slab once (halo cols stay zero forever; never filled)
    for (int q = tid; q < SLAB_B / 16; q += NTHREADS)
        ((uint4*)smraw)[q] = make_uint4(0, 0, 0, 0);

    while (true) {
        // steal a tile (syncthreads also covers slab-zero / prior-tile reads)
        __syncthreads();
        if (tid == 0)
            *steal_slot = atomicAdd(&g_ctr, 1);
        __syncthreads();
        const int tile = *steal_slot;
        if (tile >= NTILES) break;

        const int b  = tile >> 6;
        const int rg = tile & 63;
        const int h0 = rg * RG;

        // re-zero EVERY OOB row (may hold stale fill from a previous tile)
        if (rg <= 1 || rg >= 62) {
            #pragma unroll 1
            for (int rr = 0; rr < SLAB_RR; ++rr) {
                const int gr = h0 - 3 + rr;
                if (gr >= 0 && gr < HH) continue;
                for (int q = tid; q < 2 * SLAB_CC; q += NTHREADS) {
                    const int pl = q / SLAB_CC;
                    const int cc = q - pl * SLAB_CC;
                    *(uint4*)(smraw + (size_t)((pl * SLAB_RR + rr) * SLAB_CC + cc) * 16)
                        = make_uint4(0, 0, 0, 0);
                }
            }
            __syncthreads();
        }

        float acc[2][6][4];
        #pragma unroll
        for (int mt = 0; mt < 2; ++mt)
            #pragma unroll
            for (int nt = 0; nt < 6; ++nt)
                #pragma unroll
                for (int q = 0; q < 4; ++q)
                    acc[mt][nt][q] = 0.0f;

        const __half* xhb = g_xh + (size_t)b * HH * WW * CIN;
        const char*   Fbb = (const char*)(g_F + (size_t)b * NCHUNK * TAPS * 768);

        // prologue: slab fill chunk0 + filt group 0
        {
            #pragma unroll 1
            for (int rr = 0; rr < SLAB_RR; ++rr) {
                const int gr = h0 - 3 + rr;
                if (gr < 0 || gr >= HH) continue;
                const char* src = (const char*)(xhb + (size_t)gr * WW * CIN)
                                + (f_w * 6 + f_pl) * 16;
                cp16(slab_u + (uint32_t)(((f_pl * SLAB_RR + rr) * SLAB_CC + 3 + f_w) * 16), src);
            }
            for (int q = tid; q < SP * 96; q += NTHREADS)
                cp16(filt_u + q * 16, Fbb + q * 16);
            CP_COMMIT();
            CP_WAIT0();
            __syncthreads();
        }

        // mainloop: 21 groups = 3 chunks x 7 kernel rows
        #pragma unroll 1
        for (int chunk = 0; chunk < NCHUNK; ++chunk) {
            #pragma unroll 1
            for (int i = 0; i < SP; ++i) {
                const int g = chunk * SP + i;

                if (g < 3 * SP - 1) {
                    const int gn  = g + 1;
                    const int nck = gn / SP;
                    const int ni  = gn - nck * SP;
                    const char* src = Fbb + ((size_t)nck * TAPS + ni * SP) * 1536;
                    const uint32_t dstb = filt_u + (uint32_t)((gn & 1) * FBUF_B);
                    for (int q = tid; q < SP * 96; q += NTHREADS)
                        cp16(dstb + q * 16, src + q * 16);
                    CP_COMMIT();
                }

                const uint32_t fb = filt_u + (uint32_t)((g & 1) * FBUF_B) + b4off;
                const uint32_t ar = a_lane
                    + (uint32_t)((rw + i) * (SLAB_CC * 16) + col0 * 16);

                #pragma unroll
                for (int j = 0; j < SP; ++j) {
                    const uint32_t bt = fb + (uint32_t)(j * 1536);
                    uint32_t Bf[6][2];
                    ldsm_x4(Bf[0][0], Bf[0][1], Bf[1][0], Bf[1][1], bt);
                    ldsm_x4(Bf[2][0], Bf[2][1], Bf[3][0], Bf[3][1], bt + 256);
                    ldsm_x4(Bf[4][0], Bf[4][1], Bf[5][0], Bf[5][1], bt + 512);
                    #pragma unroll
                    for (int mt = 0; mt < 2; ++mt) {
                        uint32_t a0, a1, a2, a3;
                        ldsm_x4(a0, a1, a2, a3, ar + (uint32_t)((mt * 16 + j) * 16));
                        #pragma unroll
                        for (int nt = 0; nt < 6; ++nt)
                            mma_f16(acc[mt][nt], a0, a1, a2, a3, Bf[nt][0], Bf[nt][1]);
                    }
                }

                CP_WAIT0();
                __syncthreads();
            }

            if (chunk < NCHUNK - 1) {
                #pragma unroll 1
                for (int rr = 0; rr < SLAB_RR; ++rr) {
                    const int gr = h0 - 3 + rr;
                    if (gr < 0 || gr >= HH) continue;
                    const char* src = (const char*)(xhb + (size_t)gr * WW * CIN)
                                    + (f_w * 6 + (chunk + 1) * 2 + f_pl) * 16;
                    cp16(slab_u + (uint32_t)(((f_pl * SLAB_RR + rr) * SLAB_CC + 3 + f_w) * 16), src);
                }
                CP_COMMIT();
                CP_WAIT0();
                __syncthreads();
            }
        }

        // epilogue
        const int row = h0 + rw;
        #pragma unroll
        for (int nt = 0; nt < 6; ++nt) {
            const int n  = nt * 8 + 2 * t4;
            const float b0 = __ldg(&cbias[n]);
            const float b1 = __ldg(&cbias[n + 1]);
            float* y0 = y + (((size_t)b * COUT + n) * HH + row) * WW;
            float* y1 = y0 + (size_t)HH * WW;
            #pragma unroll
            for (int mt = 0; mt < 2; ++mt) {
                const int px = col0 + mt * 16 + g8;
                y0[px]     = acc[mt][nt][0] + b0;
                y1[px]     = acc[mt][nt][1] + b1;
                y0[px + 8] = acc[mt][nt][2] + b0;
                y1[px + 8] = acc[mt][nt][3] + b1;
            }
        }
    }
}

// ---------------------------------------------------------------------------
extern "C" void kernel_launch(void* const* d_in, const int* in_sizes, int n_in,
                              void* d_out, int out_size)
{
    const float* x     = (const float*)d_in[0];  // (16,48,128,128)
    const float* theta = (const float*)d_in[1];  // (16,1)
    const float* wts   = (const float*)d_in[2];  // (48,98,48)
    const float* cbias = (const float*)d_in[3];  // (1,48,1,1)
    float*       y     = (float*)d_out;          // (16,48,128,128)

    (void)in_sizes; (void)n_in; (void)out_size;

    static int grid_cached = 0;
    if (!grid_cached) {
        cudaFuncSetAttribute(conv_mma_kernel,
                             cudaFuncAttributeMaxDynamicSharedMemorySize, SMEMT);
        int dev = 0, nsm = 148, occ = 0;
        cudaGetDevice(&dev);
        cudaDeviceGetAttribute(&nsm, cudaDevAttrMultiProcessorCount, dev);
        cudaOccupancyMaxActiveBlocksPerMultiprocessor(&occ, conv_mma_kernel,
                                                      NTHREADS, SMEMT);
        if (occ < 1) occ = 1;
        int g = occ * nsm;
        if (g > NTILES) g = NTILES;
        grid_cached = g;
    }

    prep_kernel<<<2048 + 192, 256>>>(x, theta, wts);
    conv_mma_kernel<<<grid_cached, NTHREADS, SMEMT>>>(cbias, y);
}